// round 2
// baseline (speedup 1.0000x reference)
#include <cuda_runtime.h>

// 8192x8192 fp32 input, 10 3x3 SAME convs, 4 2x2 maxpools.
// Stages: [conv,conv,pool] x2 then [conv,conv,conv,pool] x2.

// Intermediate scratch (allocation-free rule: __device__ globals).
__device__ float g_buf0[4096u * 4096u];  // after stage A
__device__ float g_buf1[2048u * 2048u];  // after stage B
__device__ float g_buf2[1024u * 1024u];  // after stage C

// One fused stage: K 3x3 convs (zero-pad SAME at IMAGE boundary) + 2x2 maxpool.
// Each block produces a TO x TO tile of the pooled output.
// Pre-pool tile is S x S = 2TO x 2TO; smem region is IN x IN = (S + 2K)^2.
// Crucial correctness detail: after each conv, positions whose global coords
// lie outside the image are forced to 0 — that is the next layer's SAME padding.
template <int K>
__global__ __launch_bounds__(256)
void stage_kernel(const float* __restrict__ in, int inW,
                  float* __restrict__ out, int outW,
                  const float* __restrict__ w0,
                  const float* __restrict__ w1,
                  const float* __restrict__ w2) {
    constexpr int TO = 32;
    constexpr int S  = 2 * TO;
    constexpr int IN = S + 2 * K;
    constexpr int NT = 256;

    __shared__ float bufA[IN * IN];
    __shared__ float bufB[IN * IN];
    __shared__ float wts[K * 9];

    const int tid = threadIdx.x;

    if (tid < K * 9) {
        const float* wp = (tid < 9) ? w0 : ((tid < 18) ? w1 : w2);
        wts[tid] = wp[tid % 9];
    }

    const int gx0 = blockIdx.x * S - K;   // buffer coord -> global: g = g?0 + coord
    const int gy0 = blockIdx.y * S - K;
    const unsigned uw = (unsigned)inW;    // square image

    // Load input region with zero padding outside the image.
    for (int i = tid; i < IN * IN; i += NT) {
        int y = i / IN, x = i - y * IN;
        int gy = gy0 + y, gx = gx0 + x;
        float v = 0.0f;
        if ((unsigned)gy < uw && (unsigned)gx < uw)
            v = in[(long)gy * inW + gx];
        bufA[i] = v;
    }
    __syncthreads();

    float* src = bufA;
    float* dst = bufB;

#pragma unroll
    for (int c = 0; c < K; ++c) {
        float wr[9];
#pragma unroll
        for (int j = 0; j < 9; ++j) wr[j] = wts[c * 9 + j];

        const int lo = c + 1;             // first valid coord this layer
        const int n  = IN - 2 * (c + 1);  // valid extent per dim
        const int ns = (n + 3) / 4;       // 4-wide strips per row

        for (int i = tid; i < n * ns; i += NT) {
            int row   = i / ns;
            int sx    = (i - row * ns) * 4;
            int y     = lo + row;
            int xbase = lo + sx;

            // 3 rows x 6 cols from smem (x clamped in-bounds; clamped lanes masked below).
            float r[3][6];
#pragma unroll
            for (int dy = 0; dy < 3; ++dy) {
                const float* p = src + (y - 1 + dy) * IN;
#pragma unroll
                for (int m = 0; m < 6; ++m) {
                    int gx = xbase - 1 + m;
                    gx = gx < (IN - 1) ? gx : (IN - 1);
                    r[dy][m] = p[gx];
                }
            }

            const bool rowin = (unsigned)(gy0 + y) < uw;  // SAME padding at image edge

#pragma unroll
            for (int j = 0; j < 4; ++j) {
                float acc = r[0][j]     * wr[0] + r[0][j + 1] * wr[1] + r[0][j + 2] * wr[2]
                          + r[1][j]     * wr[3] + r[1][j + 1] * wr[4] + r[1][j + 2] * wr[5]
                          + r[2][j]     * wr[6] + r[2][j + 1] * wr[7] + r[2][j + 2] * wr[8];
                int x = xbase + j;
                // Zero out positions outside the image: exactly the reference's
                // zero padding of this layer's H x W output before the next conv.
                bool inimg = rowin && ((unsigned)(gx0 + x) < uw);
                if (x < lo + n) dst[y * IN + x] = inimg ? acc : 0.0f;
            }
        }
        __syncthreads();
        float* t = src; src = dst; dst = t;
    }

    // 2x2 max pool over the valid S x S region (offset K in buffer coords).
    for (int i = tid; i < TO * TO; i += NT) {
        int py = i / TO, px = i - py * TO;
        const float* p = src + (K + 2 * py) * IN + (K + 2 * px);
        float m = fmaxf(fmaxf(p[0], p[1]), fmaxf(p[IN], p[IN + 1]));
        out[(long)(blockIdx.y * TO + py) * outW + blockIdx.x * TO + px] = m;
    }
}

extern "C" void kernel_launch(void* const* d_in, const int* in_sizes, int n_in,
                              void* d_out, int out_size) {
    const float* x = (const float*)d_in[0];
    const float* w[10];
    for (int i = 0; i < 10; ++i) w[i] = (const float*)d_in[1 + i];

    float *b0, *b1, *b2;
    cudaGetSymbolAddress((void**)&b0, g_buf0);
    cudaGetSymbolAddress((void**)&b1, g_buf1);
    cudaGetSymbolAddress((void**)&b2, g_buf2);

    float* outp = (float*)d_out;
    dim3 blk(256);

    { dim3 grid(4096 / 32, 4096 / 32);
      stage_kernel<2><<<grid, blk>>>(x,  8192, b0,  4096, w[0], w[1], nullptr); }
    { dim3 grid(2048 / 32, 2048 / 32);
      stage_kernel<2><<<grid, blk>>>(b0, 4096, b1,  2048, w[2], w[3], nullptr); }
    { dim3 grid(1024 / 32, 1024 / 32);
      stage_kernel<3><<<grid, blk>>>(b1, 2048, b2,  1024, w[4], w[5], w[6]); }
    { dim3 grid(512 / 32, 512 / 32);
      stage_kernel<3><<<grid, blk>>>(b2, 1024, outp, 512, w[7], w[8], w[9]); }
}

// round 3
// speedup vs baseline: 1.2239x; 1.2239x over previous
#include <cuda_runtime.h>

// 8192x8192 fp32 input; 10 3x3 SAME convs; 4 2x2 maxpools.
// Stages: [conv,conv,pool] x2 then [conv,conv,conv,pool] x2.

__device__ float g_buf0[4096u * 4096u];
__device__ float g_buf1[2048u * 2048u];
__device__ float g_buf2[1024u * 1024u];

#define BROWS 72
#define BCOLS 80      // padded smem row stride (floats), 16B-aligned rows
#define NT    320     // 10 warps

// Load 8 consecutive floats (two aligned float4s) from smem.
__device__ __forceinline__ void ld8(float* d, const float* p) {
    float4 a = *(const float4*)(p);
    float4 b = *(const float4*)(p + 4);
    d[0]=a.x; d[1]=a.y; d[2]=a.z; d[3]=a.w;
    d[4]=b.x; d[5]=b.y; d[6]=b.z; d[7]=b.w;
}

// One fused stage: K 3x3 convs (SAME zero-pad at image boundary, re-applied
// after every layer) followed by 2x2 maxpool. Block computes a 32x32 pooled
// tile (64x64 pre-pool). Smem working buffer: 72 rows x 80 cols, zero-inited;
// each layer computes a fixed 68x68 region at offset (c+1); finite garbage in
// the halo never reaches the strictly-valid [K, K+64) pool window.
template <int K>
__global__ __launch_bounds__(NT)
void stage_kernel(const float* __restrict__ in, int inW,
                  float* __restrict__ out, int outW,
                  const float* __restrict__ w0,
                  const float* __restrict__ w1,
                  const float* __restrict__ w2) {
    __shared__ float bufA[BROWS * BCOLS];
    __shared__ float bufB[BROWS * BCOLS];
    __shared__ float wts[27];

    const int tid = threadIdx.x;
    if (tid < K * 9) {
        const float* wp = (tid < 9) ? w0 : ((tid < 18) ? w1 : w2);
        wts[tid] = wp[tid % 9];
    }

    const int gx0 = blockIdx.x * 64 - K;
    const int gy0 = blockIdx.y * 64 - K;
    const unsigned uw = (unsigned)inW;  // square image

    // Load input region (zero outside image / outside extent); zero bufB.
    {
        const int c  = tid % BCOLS;   // 0..79
        const int r0 = tid / BCOLS;   // 0..3
        const int EXT = 64 + 2 * K;
        const bool colin = (c < EXT) && ((unsigned)(gx0 + c) < uw);
        const long gcol = gx0 + c;
        for (int r = r0; r < BROWS; r += NT / BCOLS) {
            float v = 0.0f;
            if (colin && r < EXT && (unsigned)(gy0 + r) < uw)
                v = in[(long)(gy0 + r) * inW + gcol];
            bufA[r * BCOLS + c] = v;
            bufB[r * BCOLS + c] = 0.0f;
        }
    }
    __syncthreads();

    float* src = bufA;
    float* dst = bufB;

    // Static mapping: 17 column strips (4 cols) x 17 row groups (4 rows).
    const bool active = tid < 289;
    const int  s = tid % 17;          // column strip
    const int  g = tid / 17;          // row group

#pragma unroll
    for (int c = 0; c < K; ++c) {
        if (active) {
            float k[9];
#pragma unroll
            for (int j = 0; j < 9; ++j) k[j] = wts[c * 9 + j];

            const int colbase = (c + 1) + 4 * s;   // first output col
            const int loadcol = 4 * s;             // aligned float4 base
            const int rowtop  = c + g * 4;         // first src row needed

            bool colok[4];
#pragma unroll
            for (int q = 0; q < 4; ++q)
                colok[q] = (unsigned)(gx0 + colbase + q) < uw;

            float win[3][8];
            ld8(win[0], src + rowtop * BCOLS + loadcol);
            ld8(win[1], src + (rowtop + 1) * BCOLS + loadcol);

#pragma unroll
            for (int j = 0; j < 4; ++j) {
                ld8(win[(j + 2) % 3], src + (rowtop + 2 + j) * BCOLS + loadcol);
                const float* r0 = win[j % 3];        // row oy-1
                const float* r1 = win[(j + 1) % 3];  // row oy
                const float* r2 = win[(j + 2) % 3];  // row oy+1

                const int  oy    = (c + 1) + g * 4 + j;
                const bool rowok = (unsigned)(gy0 + oy) < uw;
                float* dp = dst + oy * BCOLS + colbase;

#pragma unroll
                for (int q = 0; q < 4; ++q) {
                    float acc = r0[c + q]     * k[0] + r0[c + q + 1] * k[1] + r0[c + q + 2] * k[2]
                              + r1[c + q]     * k[3] + r1[c + q + 1] * k[4] + r1[c + q + 2] * k[5]
                              + r2[c + q]     * k[6] + r2[c + q + 1] * k[7] + r2[c + q + 2] * k[8];
                    // SAME padding at image edge: zero outside-image positions.
                    dp[q] = (rowok && colok[q]) ? acc : 0.0f;
                }
            }
        }
        __syncthreads();
        float* t = src; src = dst; dst = t;
    }

    // 2x2 max pool over buffer region [K, K+64)^2 -> 32x32 pooled tile.
    for (int i = tid; i < 1024; i += NT) {
        int py = i >> 5, px = i & 31;
        const float* p = src + (K + 2 * py) * BCOLS + (K + 2 * px);
        float m = fmaxf(fmaxf(p[0], p[1]), fmaxf(p[BCOLS], p[BCOLS + 1]));
        out[(long)(blockIdx.y * 32 + py) * outW + blockIdx.x * 32 + px] = m;
    }
}

extern "C" void kernel_launch(void* const* d_in, const int* in_sizes, int n_in,
                              void* d_out, int out_size) {
    const float* x = (const float*)d_in[0];
    const float* w[10];
    for (int i = 0; i < 10; ++i) w[i] = (const float*)d_in[1 + i];

    float *b0, *b1, *b2;
    cudaGetSymbolAddress((void**)&b0, g_buf0);
    cudaGetSymbolAddress((void**)&b1, g_buf1);
    cudaGetSymbolAddress((void**)&b2, g_buf2);

    float* outp = (float*)d_out;
    dim3 blk(NT);

    { dim3 grid(128, 128);
      stage_kernel<2><<<grid, blk>>>(x,  8192, b0,  4096, w[0], w[1], nullptr); }
    { dim3 grid(64, 64);
      stage_kernel<2><<<grid, blk>>>(b0, 4096, b1,  2048, w[2], w[3], nullptr); }
    { dim3 grid(32, 32);
      stage_kernel<3><<<grid, blk>>>(b1, 2048, b2,  1024, w[4], w[5], w[6]); }
    { dim3 grid(16, 16);
      stage_kernel<3><<<grid, blk>>>(b2, 1024, outp, 512, w[7], w[8], w[9]); }
}